// round 2
// baseline (speedup 1.0000x reference)
#include <cuda_runtime.h>
#include <cstdint>
#include <math.h>

// Fused 3x3 same-conv (fp32, packed f32x2 FFMA) + LIF scan, plus a
// flag-and-fix pass: outputs whose membrane potential lands within 1e-4 of
// the spike threshold are recomputed with exact (fp64) convolution and
// reference-identical fp32 LIF arithmetic, eliminating this kernel's
// summation-order rounding from every near-threshold spike decision.
//
// x: [T=8, B=16, Cin=64, 64, 64] f32   w: [64, 64, 3, 3] f32
// out: spikes [8, 16, 64, 64, 64] f32

#define TT 8
#define BB 16
#define CIN 64
#define COUT 64

#define WS_FLOATS (576 * 64)        // ws[k=ci*9+ky*3+kx][co]
#define INS_FLOATS (64 * 10 * 20)   // ins[ci][10 rows][18 cols padded to 20]
#define SMEM_BYTES ((WS_FLOATS + INS_FLOATS) * 4)

#define FLAG_CAP 65536
#define FLAG_DELTA 1e-4f

__device__ int g_cnt;
__device__ int g_idx[FLAG_CAP];

__device__ __forceinline__ void fma2(unsigned long long &a,
                                     unsigned long long w,
                                     unsigned long long s) {
    asm("fma.rn.f32x2 %0, %1, %2, %0;" : "+l"(a) : "l"(w), "l"(s));
}
__device__ __forceinline__ void add2(unsigned long long &a, unsigned long long b) {
    asm("add.rn.f32x2 %0, %0, %1;" : "+l"(a) : "l"(b));
}
__device__ __forceinline__ unsigned long long splat2(float x) {
    unsigned long long r;
    unsigned u = __float_as_uint(x);
    asm("mov.b64 %0, {%1, %1};" : "=l"(r) : "r"(u));
    return r;
}

__device__ __forceinline__ void push_flag(int enc) {
    int i = atomicAdd(&g_cnt, 1);
    if (i < FLAG_CAP) g_idx[i] = enc;
}

__global__ void zero_cnt_kernel() {
    if (threadIdx.x == 0) g_cnt = 0;
}

__global__ __launch_bounds__(256, 1)
void snn_conv_lif_kernel(const float* __restrict__ x,
                         const float* __restrict__ w,
                         float* __restrict__ out)
{
    extern __shared__ float smem[];
    float* ws  = smem;               // [576][64]
    float* ins = smem + WS_FLOATS;   // [64][10][20]

    const int tid  = threadIdx.x;
    const int b    = blockIdx.x >> 5;
    const int tile = blockIdx.x & 31;
    const int ty0  = (tile >> 2) * 8;    // tile row origin (8 rows)
    const int tx0  = (tile & 3) * 16;    // tile col origin (16 cols)

    // thread -> 8 output channels (co0..co0+7 as 4 f32x2 pairs) x 4 pixels
    const int cg   = tid & 7;
    const int slot = tid >> 3;           // 0..31
    const int py   = slot >> 2;          // 0..7
    const int px0  = (slot & 3) * 4;     // 0,4,8,12
    const int co0  = cg * 8;

    // ---- load weights into smem, transposed to ws[k][co] ----
    {
        const int lco = tid >> 2;            // 0..63
        const int kb  = (tid & 3) * 144;
        const float4* wg = reinterpret_cast<const float4*>(w + lco * 576 + kb);
        #pragma unroll 4
        for (int j = 0; j < 36; ++j) {
            float4 v4 = wg[j];
            int k = kb + j * 4;
            ws[(k + 0) * 64 + lco] = v4.x;
            ws[(k + 1) * 64 + lco] = v4.y;
            ws[(k + 2) * 64 + lco] = v4.z;
            ws[(k + 3) * 64 + lco] = v4.w;
        }
    }

    float v[32];
    #pragma unroll
    for (int i = 0; i < 32; ++i) v[i] = 0.0f;

    for (int t = 0; t < TT; ++t) {
        __syncthreads();

        // ---- stage input tile (with halo, zero-padded) ----
        const float* xt = x + (size_t)(t * BB + b) * (CIN * 64 * 64);
        for (int m = tid; m < 64 * 10 * 18; m += 256) {
            int txi = m % 18;
            int rem = m / 18;
            int tyi = rem % 10;
            int ci  = rem / 10;
            int gy = ty0 + tyi - 1;
            int gx = tx0 + txi - 1;
            float val = 0.0f;
            if ((unsigned)gy < 64u && (unsigned)gx < 64u)
                val = xt[ci * 4096 + gy * 64 + gx];
            ins[(ci * 10 + tyi) * 20 + txi] = val;
        }
        __syncthreads();

        // ---- conv: packed f32x2 MACs, chunked accumulation ----
        unsigned long long accM[16];
        #pragma unroll
        for (int i = 0; i < 16; ++i) accM[i] = 0ull;

        for (int cc = 0; cc < 64; cc += 8) {
            unsigned long long accC[16];
            #pragma unroll
            for (int i = 0; i < 16; ++i) accC[i] = 0ull;

            #pragma unroll 2
            for (int ci = cc; ci < cc + 8; ++ci) {
                #pragma unroll
                for (int ky = 0; ky < 3; ++ky) {
                    const float* row = &ins[(ci * 10 + py + ky) * 20 + px0];
                    float4 ra = *reinterpret_cast<const float4*>(row);
                    float2 rb = *reinterpret_cast<const float2*>(row + 4);
                    unsigned long long sp[6];
                    sp[0] = splat2(ra.x); sp[1] = splat2(ra.y);
                    sp[2] = splat2(ra.z); sp[3] = splat2(ra.w);
                    sp[4] = splat2(rb.x); sp[5] = splat2(rb.y);
                    const int kk = (ci * 3 + ky) * 3;
                    #pragma unroll
                    for (int kx = 0; kx < 3; ++kx) {
                        const ulonglong2* wp =
                            reinterpret_cast<const ulonglong2*>(&ws[(kk + kx) * 64 + co0]);
                        ulonglong2 w01 = wp[0];
                        ulonglong2 w23 = wp[1];
                        unsigned long long wpair[4] = {w01.x, w01.y, w23.x, w23.y};
                        #pragma unroll
                        for (int p = 0; p < 4; ++p) {
                            #pragma unroll
                            for (int d = 0; d < 4; ++d)
                                fma2(accC[p * 4 + d], wpair[p], sp[kx + d]);
                        }
                    }
                }
            }
            #pragma unroll
            for (int i = 0; i < 16; ++i) add2(accM[i], accC[i]);
        }

        // ---- LIF update + near-threshold flagging + spike store ----
        float* ob = out + (size_t)((t * BB + b) * COUT) * 4096;
        const int gy = ty0 + py;
        const int gx0 = tx0 + px0;
        const size_t pix = (size_t)gy * 64 + gx0;
        #pragma unroll
        for (int p = 0; p < 4; ++p) {
            float slo[4], shi[4];
            #pragma unroll
            for (int d = 0; d < 4; ++d) {
                unsigned long long a = accM[p * 4 + d];
                float zlo = __uint_as_float((unsigned)(a & 0xffffffffull));
                float zhi = __uint_as_float((unsigned)(a >> 32));
                int ilo = (p * 4 + d) * 2, ihi = ilo + 1;
                float vl = v[ilo], vh = v[ihi];
                vl = vl + (zlo - vl) * 0.5f;   // identical rounding to ref
                vh = vh + (zhi - vh) * 0.5f;
                if (fabsf(vl - 1.0f) < FLAG_DELTA)
                    push_flag((((b * 64 + (co0 + 2 * p)) * 64 + gy) * 64) + gx0 + d);
                if (fabsf(vh - 1.0f) < FLAG_DELTA)
                    push_flag((((b * 64 + (co0 + 2 * p + 1)) * 64 + gy) * 64) + gx0 + d);
                float sl = (vl >= 1.0f) ? 1.0f : 0.0f;
                float sh = (vh >= 1.0f) ? 1.0f : 0.0f;
                v[ilo] = (vl >= 1.0f) ? 0.0f : vl;
                v[ihi] = (vh >= 1.0f) ? 0.0f : vh;
                slo[d] = sl;
                shi[d] = sh;
            }
            const int colo = co0 + 2 * p;
            *reinterpret_cast<float4*>(ob + (size_t)colo * 4096 + pix) =
                make_float4(slo[0], slo[1], slo[2], slo[3]);
            *reinterpret_cast<float4*>(ob + (size_t)(colo + 1) * 4096 + pix) =
                make_float4(shi[0], shi[1], shi[2], shi[3]);
        }
    }
}

// Recompute flagged trajectories: exact fp64 conv, round z to fp32, then
// fp32 LIF with the reference's exact op sequence. Overwrites all T spikes.
__global__ void fix_kernel(const float* __restrict__ x,
                           const float* __restrict__ w,
                           float* __restrict__ out)
{
    int n = g_cnt;
    if (n > FLAG_CAP) n = FLAG_CAP;
    for (int i = blockIdx.x * blockDim.x + threadIdx.x; i < n;
         i += gridDim.x * blockDim.x) {
        int e = g_idx[i];
        int xp = e & 63;
        int y  = (e >> 6) & 63;
        int co = (e >> 12) & 63;
        int b  = e >> 18;
        const float* wr = w + co * 576;
        float v = 0.0f;
        for (int t = 0; t < TT; ++t) {
            const float* xt = x + (size_t)(t * BB + b) * (CIN * 64 * 64);
            double z = 0.0;
            for (int ci = 0; ci < 64; ++ci) {
                for (int ky = 0; ky < 3; ++ky) {
                    int gy = y + ky - 1;
                    if ((unsigned)gy >= 64u) continue;
                    const float* xr = xt + ci * 4096 + gy * 64;
                    const float* wk = wr + ci * 9 + ky * 3;
                    for (int kx = 0; kx < 3; ++kx) {
                        int gx = xp + kx - 1;
                        if ((unsigned)gx >= 64u) continue;
                        z += (double)xr[gx] * (double)wk[kx];
                    }
                }
            }
            float zf = (float)z;
            v = v + (zf - v) * 0.5f;
            float s = (v >= 1.0f) ? 1.0f : 0.0f;
            v = (v >= 1.0f) ? 0.0f : v;
            out[((size_t)(t * BB + b) * COUT + co) * 4096 + y * 64 + xp] = s;
        }
    }
}

extern "C" void kernel_launch(void* const* d_in, const int* in_sizes, int n_in,
                              void* d_out, int out_size) {
    const float* x  = (const float*)d_in[0];
    const float* w  = (const float*)d_in[1];
    float* out      = (float*)d_out;
    cudaFuncSetAttribute(snn_conv_lif_kernel,
                         cudaFuncAttributeMaxDynamicSharedMemorySize, SMEM_BYTES);
    zero_cnt_kernel<<<1, 32>>>();
    snn_conv_lif_kernel<<<512, 256, SMEM_BYTES>>>(x, w, out);
    fix_kernel<<<128, 128>>>(x, w, out);
}

// round 3
// speedup vs baseline: 3.0502x; 3.0502x over previous
#include <cuda_runtime.h>
#include <cstdint>
#include <math.h>

// Fused 3x3 same-conv (fp32, packed f32x2 FFMA) + LIF scan + flag-and-fix.
//
// Round-2 change: warp-uniform output channels (co0 = warpid*8), pixels
// across lanes. Weight LDS becomes a warp broadcast -> smem crossbar traffic
// drops ~4.4x and the kernel becomes FMA-issue-bound instead of smem-bound.
//
// x: [T=8, B=16, Cin=64, 64, 64] f32   w: [64, 64, 3, 3] f32
// out: spikes [8, 16, 64, 64, 64] f32

#define TT 8
#define BB 16
#define CIN 64
#define COUT 64

#define WS_FLOATS (576 * 64)        // ws[k=ci*9+ky*3+kx][co]
#define INS_FLOATS (64 * 10 * 20)   // ins[ci][10 rows][18 cols padded to 20]
#define SMEM_BYTES ((WS_FLOATS + INS_FLOATS) * 4)

#define FLAG_CAP 65536
#define FLAG_DELTA 2e-5f

__device__ int g_cnt;    // zero-initialized at module load; reset by fixer
__device__ int g_done;
__device__ int g_idx[FLAG_CAP];

__device__ __forceinline__ void fma2(unsigned long long &a,
                                     unsigned long long w,
                                     unsigned long long s) {
    asm("fma.rn.f32x2 %0, %1, %2, %0;" : "+l"(a) : "l"(w), "l"(s));
}
__device__ __forceinline__ unsigned long long splat2(float x) {
    unsigned long long r;
    unsigned u = __float_as_uint(x);
    asm("mov.b64 %0, {%1, %1};" : "=l"(r) : "r"(u));
    return r;
}
__device__ __forceinline__ void push_flag(int enc) {
    int i = atomicAdd(&g_cnt, 1);
    if (i < FLAG_CAP) g_idx[i] = enc;
}

__global__ __launch_bounds__(256, 1)
void snn_conv_lif_kernel(const float* __restrict__ x,
                         const float* __restrict__ w,
                         float* __restrict__ out)
{
    extern __shared__ float smem[];
    float* ws  = smem;               // [576][64]
    float* ins = smem + WS_FLOATS;   // [64][10][20]

    const int tid  = threadIdx.x;
    const int b    = blockIdx.x >> 5;
    const int tile = blockIdx.x & 31;
    const int ty0  = (tile >> 2) * 8;    // tile row origin (8 rows)
    const int tx0  = (tile & 3) * 16;    // tile col origin (16 cols)

    // NEW MAP: warp-uniform co, lanes = pixels.
    const int warp = tid >> 5;           // 0..7
    const int lane = tid & 31;
    const int co0  = warp * 8;           // 8 co per warp (4 f32x2 pairs)
    const int py   = lane >> 2;          // 0..7
    const int px0  = (lane & 3) * 4;     // 0,4,8,12

    // ---- load weights into smem, transposed to ws[k][co] ----
    {
        const int lco = tid >> 2;            // 0..63
        const int kb  = (tid & 3) * 144;
        const float4* wg = reinterpret_cast<const float4*>(w + lco * 576 + kb);
        #pragma unroll 4
        for (int j = 0; j < 36; ++j) {
            float4 v4 = wg[j];
            int k = kb + j * 4;
            ws[(k + 0) * 64 + lco] = v4.x;
            ws[(k + 1) * 64 + lco] = v4.y;
            ws[(k + 2) * 64 + lco] = v4.z;
            ws[(k + 3) * 64 + lco] = v4.w;
        }
    }

    float v[32];
    #pragma unroll
    for (int i = 0; i < 32; ++i) v[i] = 0.0f;

    for (int t = 0; t < TT; ++t) {
        __syncthreads();  // prev readers done (fences weight load at t=0)

        // ---- stage input tile (with halo, zero-padded) ----
        const float* xt = x + (size_t)(t * BB + b) * (CIN * 64 * 64);
        for (int m = tid; m < 64 * 10 * 18; m += 256) {
            int txi = m % 18;
            int rem = m / 18;
            int tyi = rem % 10;
            int ci  = rem / 10;
            int gy = ty0 + tyi - 1;
            int gx = tx0 + txi - 1;
            float val = 0.0f;
            if ((unsigned)gy < 64u && (unsigned)gx < 64u)
                val = xt[ci * 4096 + gy * 64 + gx];
            ins[(ci * 10 + tyi) * 20 + txi] = val;
        }
        __syncthreads();

        // ---- conv: packed f32x2 MACs, broadcast weight loads ----
        unsigned long long acc[16];
        #pragma unroll
        for (int i = 0; i < 16; ++i) acc[i] = 0ull;

        #pragma unroll 4
        for (int ci = 0; ci < 64; ++ci) {
            #pragma unroll
            for (int ky = 0; ky < 3; ++ky) {
                const float* row = &ins[(ci * 10 + py + ky) * 20 + px0];
                float4 ra = *reinterpret_cast<const float4*>(row);
                float2 rb = *reinterpret_cast<const float2*>(row + 4);
                unsigned long long sp[6];
                sp[0] = splat2(ra.x); sp[1] = splat2(ra.y);
                sp[2] = splat2(ra.z); sp[3] = splat2(ra.w);
                sp[4] = splat2(rb.x); sp[5] = splat2(rb.y);
                const int kk = (ci * 3 + ky) * 3;
                #pragma unroll
                for (int kx = 0; kx < 3; ++kx) {
                    // warp-uniform address -> broadcast, conflict-free
                    const ulonglong2* wp =
                        reinterpret_cast<const ulonglong2*>(&ws[(kk + kx) * 64 + co0]);
                    ulonglong2 w01 = wp[0];
                    ulonglong2 w23 = wp[1];
                    unsigned long long wpair[4] = {w01.x, w01.y, w23.x, w23.y};
                    #pragma unroll
                    for (int p = 0; p < 4; ++p) {
                        #pragma unroll
                        for (int d = 0; d < 4; ++d)
                            fma2(acc[p * 4 + d], wpair[p], sp[kx + d]);
                    }
                }
            }
        }

        // ---- LIF update + near-threshold flagging + spike store ----
        float* ob = out + (size_t)((t * BB + b) * COUT) * 4096;
        const int gy = ty0 + py;
        const int gx0 = tx0 + px0;
        const size_t pix = (size_t)gy * 64 + gx0;
        #pragma unroll
        for (int p = 0; p < 4; ++p) {
            float slo[4], shi[4];
            #pragma unroll
            for (int d = 0; d < 4; ++d) {
                unsigned long long a = acc[p * 4 + d];
                float zlo = __uint_as_float((unsigned)(a & 0xffffffffull));
                float zhi = __uint_as_float((unsigned)(a >> 32));
                int ilo = (p * 4 + d) * 2, ihi = ilo + 1;
                float vl = v[ilo], vh = v[ihi];
                vl = vl + (zlo - vl) * 0.5f;   // identical rounding to ref
                vh = vh + (zhi - vh) * 0.5f;
                if (fabsf(vl - 1.0f) < FLAG_DELTA)
                    push_flag((((b * 64 + (co0 + 2 * p)) * 64 + gy) * 64) + gx0 + d);
                if (fabsf(vh - 1.0f) < FLAG_DELTA)
                    push_flag((((b * 64 + (co0 + 2 * p + 1)) * 64 + gy) * 64) + gx0 + d);
                float sl = (vl >= 1.0f) ? 1.0f : 0.0f;
                float sh = (vh >= 1.0f) ? 1.0f : 0.0f;
                v[ilo] = (vl >= 1.0f) ? 0.0f : vl;
                v[ihi] = (vh >= 1.0f) ? 0.0f : vh;
                slo[d] = sl;
                shi[d] = sh;
            }
            const int colo = co0 + 2 * p;
            *reinterpret_cast<float4*>(ob + (size_t)colo * 4096 + pix) =
                make_float4(slo[0], slo[1], slo[2], slo[3]);
            *reinterpret_cast<float4*>(ob + (size_t)(colo + 1) * 4096 + pix) =
                make_float4(shi[0], shi[1], shi[2], shi[3]);
        }
    }
}

// Warp-per-trajectory fixer: fp64 conv (lane-parallel taps + deterministic
// shuffle tree-reduce), round z to fp32, reference-identical fp32 LIF.
// Last finished block resets g_cnt/g_done so the graph is replay-safe.
__global__ void fix_kernel(const float* __restrict__ x,
                           const float* __restrict__ w,
                           float* __restrict__ out)
{
    int n = g_cnt;
    if (n > FLAG_CAP) n = FLAG_CAP;
    const int lane = threadIdx.x & 31;
    const int wid  = (blockIdx.x * blockDim.x + threadIdx.x) >> 5;
    const int nw   = (gridDim.x * blockDim.x) >> 5;

    for (int i = wid; i < n; i += nw) {
        int e = g_idx[i];
        int xp = e & 63;
        int y  = (e >> 6) & 63;
        int co = (e >> 12) & 63;
        int b  = e >> 18;
        const float* wr = w + co * 576;
        const int ci0 = lane * 2;         // 2 input channels per lane
        float v = 0.0f;
        for (int t = 0; t < TT; ++t) {
            const float* xt = x + (size_t)(t * BB + b) * (CIN * 64 * 64);
            double z = 0.0;
            #pragma unroll
            for (int cc = 0; cc < 2; ++cc) {
                int ci = ci0 + cc;
                #pragma unroll
                for (int ky = 0; ky < 3; ++ky) {
                    int gy = y + ky - 1;
                    if ((unsigned)gy >= 64u) continue;
                    const float* xr = xt + ci * 4096 + gy * 64;
                    const float* wk = wr + ci * 9 + ky * 3;
                    #pragma unroll
                    for (int kx = 0; kx < 3; ++kx) {
                        int gx = xp + kx - 1;
                        if ((unsigned)gx >= 64u) continue;
                        z += (double)xr[gx] * (double)wk[kx];
                    }
                }
            }
            // deterministic warp tree-reduce (fp64)
            #pragma unroll
            for (int off = 16; off > 0; off >>= 1)
                z += __shfl_down_sync(0xffffffffu, z, off);
            if (lane == 0) {
                float zf = (float)z;
                v = v + (zf - v) * 0.5f;
                float s = (v >= 1.0f) ? 1.0f : 0.0f;
                v = (v >= 1.0f) ? 0.0f : v;
                out[((size_t)(t * BB + b) * COUT + co) * 4096 + y * 64 + xp] = s;
            }
        }
    }

    __syncthreads();
    if (threadIdx.x == 0) {
        __threadfence();
        int d = atomicAdd(&g_done, 1);
        if (d == (int)gridDim.x - 1) {
            g_cnt = 0;
            g_done = 0;
            __threadfence();
        }
    }
}

extern "C" void kernel_launch(void* const* d_in, const int* in_sizes, int n_in,
                              void* d_out, int out_size) {
    const float* x  = (const float*)d_in[0];
    const float* w  = (const float*)d_in[1];
    float* out      = (float*)d_out;
    cudaFuncSetAttribute(snn_conv_lif_kernel,
                         cudaFuncAttributeMaxDynamicSharedMemorySize, SMEM_BYTES);
    snn_conv_lif_kernel<<<512, 256, SMEM_BYTES>>>(x, w, out);
    fix_kernel<<<256, 128>>>(x, w, out);
}

// round 5
// speedup vs baseline: 3.3681x; 1.1042x over previous
#include <cuda_runtime.h>
#include <cstdint>
#include <math.h>

// Fused 3x3 conv via warp-level tf32 tensor-core MMA (mma.sync.m16n8k8,
// compute_100-compatible) + LIF scan in registers + flag-and-fix.
//
// x: [T=8, B=16, Cin=64, 64, 64] f32   w: [64, 64, 3, 3] f32
// out: spikes [8, 16, 64, 64, 64] f32
//
// Implicit GEMM per CTA tile (128 px x 64 co), k = tap*64 + ci (576 total).
// Bank-conflict-free pitches: input ci-pitch 184 words, weight k-pitch 72.

#define TT 8
#define BB 16

#define W_PITCH 72
#define CI_PITCH 184
#define SM_W_WORDS (576 * W_PITCH)                 // 41472 words
#define SMEM_WORDS (SM_W_WORDS + 64 * CI_PITCH)    // + 11776 = 53248
#define SMEM_BYTES (SMEM_WORDS * 4)                // 212992 B

#define FLAG_CAP 131072
#define FLAG_DELTA 1.5e-3f

__device__ int g_cnt;    // zeroed at module load; reset by fix_kernel
__device__ int g_done;
__device__ int g_idx[FLAG_CAP];

__device__ __forceinline__ uint32_t f2tf32(float x) {
    uint32_t r;
    asm("cvt.rna.tf32.f32 %0, %1;" : "=r"(r) : "f"(x));
    return r;
}
__device__ __forceinline__ void mma8(float* c, const uint32_t* a,
                                     uint32_t b0, uint32_t b1) {
    asm volatile(
        "mma.sync.aligned.m16n8k8.row.col.f32.tf32.tf32.f32 "
        "{%0,%1,%2,%3}, {%4,%5,%6,%7}, {%8,%9}, {%0,%1,%2,%3};"
        : "+f"(c[0]), "+f"(c[1]), "+f"(c[2]), "+f"(c[3])
        : "r"(a[0]), "r"(a[1]), "r"(a[2]), "r"(a[3]), "r"(b0), "r"(b1));
}
__device__ __forceinline__ void push_flag(int enc) {
    int i = atomicAdd(&g_cnt, 1);
    if (i < FLAG_CAP) g_idx[i] = enc;
}

__global__ __launch_bounds__(256, 1)
void snn_conv_lif_kernel(const float* __restrict__ x,
                         const float* __restrict__ w,
                         float* __restrict__ out)
{
    extern __shared__ float smem[];
    float* wsm = smem;                    // [k=576][co, pitch 72] tf32 bits
    float* ins = smem + SM_W_WORDS;       // [ci=64, pitch 184][10y][18x] tf32 bits
    uint32_t* wsmU = reinterpret_cast<uint32_t*>(wsm);
    uint32_t* insU = reinterpret_cast<uint32_t*>(ins);

    const int tid  = threadIdx.x;
    const int wid  = tid >> 5;
    const int lane = tid & 31;
    const int gid  = lane >> 2;          // 0..7
    const int tig  = lane & 3;           // 0..3
    const int b    = blockIdx.x >> 5;
    const int tile = blockIdx.x & 31;
    const int ty0  = (tile >> 2) * 8;    // tile row origin (8 rows)
    const int tx0  = (tile & 3) * 16;    // tile col origin (16 cols)

    const int warpM = wid & 3;           // M chunk of 32 px  (2 y-rows)
    const int warpN = wid >> 2;          // N chunk of 32 co

    // ---- stage weights: w[co][ci][ky][kx] -> wsm[(tap*64+ci)*72 + co] ----
    for (int idx = tid; idx < 64 * 64 * 9; idx += 256) {
        int co  = idx / 576;
        int r   = idx % 576;
        int ci  = r / 9;
        int tap = r % 9;
        wsmU[(tap * 64 + ci) * W_PITCH + co] = f2tf32(w[idx]);
    }

    float v[32];
    #pragma unroll
    for (int i = 0; i < 32; ++i) v[i] = 0.0f;

    for (int t = 0; t < TT; ++t) {
        __syncthreads();   // prev compute done (fences weight staging at t=0)

        // ---- stage input tile (tf32, zero-padded halo) ----
        const float* xt = x + (size_t)(t * BB + b) * (64 * 64 * 64);
        for (int m = tid; m < 64 * 10 * 18; m += 256) {
            int txi = m % 18;
            int rem = m / 18;
            int tyi = rem % 10;
            int ci  = rem / 10;
            int gy = ty0 + tyi - 1;
            int gx = tx0 + txi - 1;
            float val = 0.0f;
            if ((unsigned)gy < 64u && (unsigned)gx < 64u)
                val = xt[ci * 4096 + gy * 64 + gx];
            insU[ci * CI_PITCH + tyi * 18 + txi] = f2tf32(val);
        }
        __syncthreads();

        // ---- implicit GEMM: acc[mt*16 + nt*4 + r] ----
        float acc[32];
        #pragma unroll
        for (int i = 0; i < 32; ++i) acc[i] = 0.0f;

        #pragma unroll 1
        for (int tap = 0; tap < 9; ++tap) {
            const int ky = tap / 3, kx = tap % 3;
            const int aoff0 = (warpM * 2 + ky) * 18 + kx + gid; // mt=0 row base
            const int koff  = tap * 64;

            #pragma unroll 2
            for (int kb = 0; kb < 8; ++kb) {
                const int ci0 = kb * 8 + tig;
                // A fragments for mt=0,1  (rows = px gid / gid+8, cols = ci0/+4)
                uint32_t a[2][4];
                #pragma unroll
                for (int mt = 0; mt < 2; ++mt) {
                    const int base = ci0 * CI_PITCH + aoff0 + mt * 18;
                    a[mt][0] = insU[base];
                    a[mt][1] = insU[base + 8];
                    a[mt][2] = insU[base + 4 * CI_PITCH];
                    a[mt][3] = insU[base + 4 * CI_PITCH + 8];
                }
                // B fragments + MMAs
                const int kk = (koff + ci0) * W_PITCH + warpN * 32 + gid;
                #pragma unroll
                for (int nt = 0; nt < 4; ++nt) {
                    uint32_t b0 = wsmU[kk + nt * 8];
                    uint32_t b1 = wsmU[kk + nt * 8 + 4 * W_PITCH];
                    mma8(&acc[nt * 4],      a[0], b0, b1);
                    mma8(&acc[16 + nt * 4], a[1], b0, b1);
                }
            }
        }

        // ---- LIF update + near-threshold flagging + spike store ----
        float* obase = out + (size_t)(t * BB + b) * (64 * 4096);
        #pragma unroll
        for (int mt = 0; mt < 2; ++mt) {
            const int yg = ty0 + warpM * 2 + mt;
            #pragma unroll
            for (int nt = 0; nt < 4; ++nt) {
                #pragma unroll
                for (int r = 0; r < 4; ++r) {
                    const int co = warpN * 32 + nt * 8 + 2 * tig + (r & 1);
                    const int xg = tx0 + gid + ((r & 2) ? 8 : 0);
                    const int vi = mt * 16 + nt * 4 + r;
                    float z = acc[vi];
                    float vv = v[vi];
                    vv = vv + (z - vv) * 0.5f;   // TAU=2, reference op order
                    if (fabsf(vv - 1.0f) < FLAG_DELTA)
                        push_flag((((b * 64 + co) * 64 + yg) * 64) + xg);
                    float s = (vv >= 1.0f) ? 1.0f : 0.0f;
                    v[vi] = (vv >= 1.0f) ? 0.0f : vv;
                    obase[(size_t)co * 4096 + yg * 64 + xg] = s;
                }
            }
        }
    }
}

// ---------------- flag-and-fix ----------------
// Warp-per-trajectory: exact fp64 conv (lane-split ci + shuffle reduce),
// round z to fp32, reference-identical fp32 LIF. Overwrites all T spikes.
// Last block resets g_cnt/g_done so the captured graph is replay-safe.
__global__ void fix_kernel(const float* __restrict__ x,
                           const float* __restrict__ w,
                           float* __restrict__ out)
{
    int n = g_cnt;
    if (n > FLAG_CAP) n = FLAG_CAP;
    const int lane = threadIdx.x & 31;
    const int wid  = (blockIdx.x * blockDim.x + threadIdx.x) >> 5;
    const int nw   = (gridDim.x * blockDim.x) >> 5;

    for (int i = wid; i < n; i += nw) {
        int e = g_idx[i];
        int xp = e & 63;
        int y  = (e >> 6) & 63;
        int co = (e >> 12) & 63;
        int b  = e >> 18;
        const float* wr = w + co * 576;
        const int ci0 = lane * 2;
        float v = 0.0f;
        for (int t = 0; t < TT; ++t) {
            const float* xt = x + (size_t)(t * BB + b) * (64 * 64 * 64);
            double z = 0.0;
            #pragma unroll
            for (int cc = 0; cc < 2; ++cc) {
                int ci = ci0 + cc;
                #pragma unroll
                for (int ky = 0; ky < 3; ++ky) {
                    int gy = y + ky - 1;
                    if ((unsigned)gy >= 64u) continue;
                    const float* xr = xt + ci * 4096 + gy * 64;
                    const float* wk = wr + ci * 9 + ky * 3;
                    #pragma unroll
                    for (int kx = 0; kx < 3; ++kx) {
                        int gx = xp + kx - 1;
                        if ((unsigned)gx >= 64u) continue;
                        z += (double)xr[gx] * (double)wk[kx];
                    }
                }
            }
            #pragma unroll
            for (int off = 16; off > 0; off >>= 1)
                z += __shfl_down_sync(0xffffffffu, z, off);
            if (lane == 0) {
                float zf = (float)z;
                v = v + (zf - v) * 0.5f;
                float s = (v >= 1.0f) ? 1.0f : 0.0f;
                v = (v >= 1.0f) ? 0.0f : v;
                out[((size_t)(t * BB + b) * 64 + co) * 4096 + y * 64 + xp] = s;
            }
        }
    }

    __syncthreads();
    if (threadIdx.x == 0) {
        __threadfence();
        int d = atomicAdd(&g_done, 1);
        if (d == (int)gridDim.x - 1) {
            g_cnt = 0;
            g_done = 0;
            __threadfence();
        }
    }
}

extern "C" void kernel_launch(void* const* d_in, const int* in_sizes, int n_in,
                              void* d_out, int out_size) {
    const float* x  = (const float*)d_in[0];
    const float* w  = (const float*)d_in[1];
    float* out      = (float*)d_out;
    cudaFuncSetAttribute(snn_conv_lif_kernel,
                         cudaFuncAttributeMaxDynamicSharedMemorySize, SMEM_BYTES);
    snn_conv_lif_kernel<<<512, 256, SMEM_BYTES>>>(x, w, out);
    fix_kernel<<<256, 256>>>(x, w, out);
}